// round 1
// baseline (speedup 1.0000x reference)
#include <cuda_runtime.h>
#include <cuda_bf16.h>
#include <mma.h>

using namespace nvcuda;

// Problem constants
#define BATCH 16
#define C_IN 384
#define C_HID 1536        // EXP*C
#define HW 1024           // 32*32
#define EMB_D 1024
#define N_GROUPS 32
#define C_PER_G 12        // 384/32
#define GN_EPS 1e-5f

// Scratch (device globals; no allocations allowed)
__device__ float g_h[BATCH * C_HID * HW];       // 96 MB hidden activations
__device__ float g_na[BATCH * C_IN];            // GN affine scale per (b,c)
__device__ float g_nb[BATCH * C_IN];            // GN affine bias per (b,c)
__device__ float g_scale[BATCH * C_HID];        // FiLM scale
__device__ float g_shift[BATCH * C_HID];        // FiLM shift

// ---------------------------------------------------------------------------
// K1: GroupNorm statistics -> fold (mean, rstd, gn_w, gn_b) into per-(b,c)
//     affine:  xn = x * g_na + g_nb
// One block per (b, group). Reduces 12*1024 = 12288 floats.
// ---------------------------------------------------------------------------
__global__ void gn_stats_kernel(const float* __restrict__ x,
                                const float* __restrict__ gw,
                                const float* __restrict__ gb) {
    int b = blockIdx.x >> 5;
    int g = blockIdx.x & 31;
    const float4* p = (const float4*)(x + ((size_t)(b * C_IN + g * C_PER_G)) * HW);

    float s = 0.f, q = 0.f;
    for (int i = threadIdx.x; i < (C_PER_G * HW) / 4; i += 256) {
        float4 v = p[i];
        s += v.x + v.y + v.z + v.w;
        q += v.x * v.x + v.y * v.y + v.z * v.z + v.w * v.w;
    }
    __shared__ float ss[256], sq[256];
    ss[threadIdx.x] = s; sq[threadIdx.x] = q;
    __syncthreads();
    for (int o = 128; o; o >>= 1) {
        if (threadIdx.x < o) {
            ss[threadIdx.x] += ss[threadIdx.x + o];
            sq[threadIdx.x] += sq[threadIdx.x + o];
        }
        __syncthreads();
    }
    __shared__ float smu, srs;
    if (threadIdx.x == 0) {
        const float inv_n = 1.f / (float)(C_PER_G * HW);
        float mu = ss[0] * inv_n;
        float var = sq[0] * inv_n - mu * mu;
        smu = mu;
        srs = rsqrtf(var + GN_EPS);
    }
    __syncthreads();
    if (threadIdx.x < C_PER_G) {
        int c = g * C_PER_G + threadIdx.x;
        float a = srs * gw[c];
        g_na[b * C_IN + c] = a;
        g_nb[b * C_IN + c] = gb[c] - smu * a;
    }
}

// ---------------------------------------------------------------------------
// K2: emb_out = emb @ we^T + be  -> split into g_scale / g_shift
// One warp per output row j (3072 rows). we row held in registers,
// reused across all 16 batches (emb rows live in L1/L2).
// ---------------------------------------------------------------------------
__global__ void emb_gemm_kernel(const float* __restrict__ emb,
                                const float* __restrict__ we,
                                const float* __restrict__ be) {
    int w = (blockIdx.x * blockDim.x + threadIdx.x) >> 5;  // global warp = row j
    int lane = threadIdx.x & 31;
    if (w >= 2 * C_HID) return;

    const float4* wr = (const float4*)(we + (size_t)w * EMB_D);
    float4 wv[8];
#pragma unroll
    for (int i = 0; i < 8; i++) wv[i] = wr[i * 32 + lane];
    float bias = be[w];

    for (int b = 0; b < BATCH; b++) {
        const float4* er = (const float4*)(emb + (size_t)b * EMB_D);
        float d = 0.f;
#pragma unroll
        for (int i = 0; i < 8; i++) {
            float4 e = er[i * 32 + lane];
            d += wv[i].x * e.x + wv[i].y * e.y + wv[i].z * e.z + wv[i].w * e.w;
        }
#pragma unroll
        for (int o = 16; o; o >>= 1) d += __shfl_xor_sync(0xffffffffu, d, o);
        if (lane == 0) {
            float v = d + bias;
            if (w < C_HID) g_scale[b * C_HID + w] = v;
            else           g_shift[b * C_HID + (w - C_HID)] = v;
        }
    }
}

// ---------------------------------------------------------------------------
// K3: out = x + b2[o]   (so GEMM2 can accumulate in place)
// ---------------------------------------------------------------------------
__global__ void out_init_kernel(const float* __restrict__ x,
                                const float* __restrict__ b2,
                                float* __restrict__ out) {
    size_t i4 = (size_t)blockIdx.x * blockDim.x + threadIdx.x;  // one float4 each
    float4 v = ((const float4*)x)[i4];
    int o = (int)((i4 >> 8) % C_IN);   // HW/4 = 256 float4 per row
    float bb = b2[o];
    v.x += bb; v.y += bb; v.z += bb; v.w += bb;
    ((float4*)out)[i4] = v;
}

// ---------------------------------------------------------------------------
// K5: h = silu(h + b1[o]) * (1 + scale[b,o]) + shift[b,o], in-place on g_h
// ---------------------------------------------------------------------------
__global__ void mod_silu_kernel(const float* __restrict__ b1) {
    size_t i4 = (size_t)blockIdx.x * blockDim.x + threadIdx.x;  // one float4 each
    float4* hp = (float4*)g_h;
    float4 v = hp[i4];
    int row = (int)(i4 >> 8);          // b*C_HID + o
    int o = row % C_HID;
    int b = row / C_HID;
    float bias = b1[o];
    float sc = 1.f + g_scale[b * C_HID + o];
    float sh = g_shift[b * C_HID + o];

    float t;
    t = v.x + bias; t = t / (1.f + __expf(-t)); v.x = t * sc + sh;
    t = v.y + bias; t = t / (1.f + __expf(-t)); v.y = t * sc + sh;
    t = v.z + bias; t = t / (1.f + __expf(-t)); v.z = t * sc + sh;
    t = v.w + bias; t = t / (1.f + __expf(-t)); v.w = t * sc + sh;
    hp[i4] = v;
}

// ---------------------------------------------------------------------------
// TF32 WMMA GEMM:  C[b] (+)= A(M x K) @ B[b](K x 1024)
//   A: weights, row-major, shared across batch
//   B: activations [b][k][hw], hw contiguous (N = 1024)
//   GN_B:    apply per-(b,k) affine to B elements while staging
//   ACC_OUT: initialize accumulators from Cdst (residual accumulate)
// Block tile 128x128x32, 8 warps, warp tile 64x32 (4x2 m16n16k8 frags).
// ---------------------------------------------------------------------------
template <int KTOT, bool GN_B, bool ACC_OUT>
__global__ void __launch_bounds__(256)
gemm_tc_kernel(const float* __restrict__ A,
               const float* __restrict__ Bsrc,
               float* __restrict__ Cdst) {
    constexpr int LDA_S = 40;    // 32 + pad, multiple of 8
    constexpr int LDB_S = 136;   // 128 + pad, multiple of 8
    __shared__ float As[128 * LDA_S];
    __shared__ float Bs[32 * LDB_S];

    const int b = blockIdx.z;
    const int m0 = blockIdx.y * 128;
    const int n0 = blockIdx.x * 128;
    const int Mtot = gridDim.y * 128;

    const float* Bg = Bsrc + (size_t)b * KTOT * HW;
    float* Cg = Cdst + (size_t)b * Mtot * HW;

    const int tid = threadIdx.x;
    const int warp = tid >> 5;
    const int wm = warp >> 2;     // 0..1  (64-row slab)
    const int wn = warp & 3;      // 0..3  (32-col slab)

    const float* na = g_na + b * C_IN;
    const float* nb = g_nb + b * C_IN;

    wmma::fragment<wmma::accumulator, 16, 16, 8, float> acc[4][2];
    if (ACC_OUT) {
#pragma unroll
        for (int i = 0; i < 4; i++)
#pragma unroll
            for (int j = 0; j < 2; j++)
                wmma::load_matrix_sync(
                    acc[i][j],
                    Cg + (size_t)(m0 + wm * 64 + i * 16) * HW + n0 + wn * 32 + j * 16,
                    HW, wmma::mem_row_major);
    } else {
#pragma unroll
        for (int i = 0; i < 4; i++)
#pragma unroll
            for (int j = 0; j < 2; j++)
                wmma::fill_fragment(acc[i][j], 0.f);
    }

    for (int k0 = 0; k0 < KTOT; k0 += 32) {
        // Stage A tile 128x32 (w row-major, lda = KTOT), convert to tf32
#pragma unroll
        for (int i = 0; i < 4; i++) {
            int f = tid + i * 256;
            int r = f >> 3;
            int kc = (f & 7) * 4;
            float4 v = *(const float4*)(A + (size_t)(m0 + r) * KTOT + k0 + kc);
            float* d = &As[r * LDA_S + kc];
            d[0] = wmma::__float_to_tf32(v.x);
            d[1] = wmma::__float_to_tf32(v.y);
            d[2] = wmma::__float_to_tf32(v.z);
            d[3] = wmma::__float_to_tf32(v.w);
        }
        // Stage B tile 32x128 (activations, hw contiguous), optional GN affine
#pragma unroll
        for (int i = 0; i < 4; i++) {
            int f = tid + i * 256;
            int r = f >> 5;
            int c4 = (f & 31) * 4;
            float4 v = *(const float4*)(Bg + (size_t)(k0 + r) * HW + n0 + c4);
            if (GN_B) {
                float a = na[k0 + r], bb = nb[k0 + r];
                v.x = v.x * a + bb; v.y = v.y * a + bb;
                v.z = v.z * a + bb; v.w = v.w * a + bb;
            }
            float* d = &Bs[r * LDB_S + c4];
            d[0] = wmma::__float_to_tf32(v.x);
            d[1] = wmma::__float_to_tf32(v.y);
            d[2] = wmma::__float_to_tf32(v.z);
            d[3] = wmma::__float_to_tf32(v.w);
        }
        __syncthreads();

#pragma unroll
        for (int kk = 0; kk < 4; kk++) {
            wmma::fragment<wmma::matrix_a, 16, 16, 8, wmma::precision::tf32, wmma::row_major> af[4];
            wmma::fragment<wmma::matrix_b, 16, 16, 8, wmma::precision::tf32, wmma::row_major> bf[2];
#pragma unroll
            for (int i = 0; i < 4; i++)
                wmma::load_matrix_sync(af[i], &As[(wm * 64 + i * 16) * LDA_S + kk * 8], LDA_S);
#pragma unroll
            for (int j = 0; j < 2; j++)
                wmma::load_matrix_sync(bf[j], &Bs[(kk * 8) * LDB_S + wn * 32 + j * 16], LDB_S);
#pragma unroll
            for (int i = 0; i < 4; i++)
#pragma unroll
                for (int j = 0; j < 2; j++)
                    wmma::mma_sync(acc[i][j], af[i], bf[j], acc[i][j]);
        }
        __syncthreads();
    }

#pragma unroll
    for (int i = 0; i < 4; i++)
#pragma unroll
        for (int j = 0; j < 2; j++)
            wmma::store_matrix_sync(
                Cg + (size_t)(m0 + wm * 64 + i * 16) * HW + n0 + wn * 32 + j * 16,
                acc[i][j], HW, wmma::mem_row_major);
}

// ---------------------------------------------------------------------------
extern "C" void kernel_launch(void* const* d_in, const int* in_sizes, int n_in,
                              void* d_out, int out_size) {
    const float* x    = (const float*)d_in[0];
    const float* emb  = (const float*)d_in[1];
    const float* gn_w = (const float*)d_in[2];
    const float* gn_b = (const float*)d_in[3];
    const float* w1   = (const float*)d_in[4];
    const float* b1   = (const float*)d_in[5];
    const float* we   = (const float*)d_in[6];
    const float* be   = (const float*)d_in[7];
    const float* w2   = (const float*)d_in[8];
    const float* b2   = (const float*)d_in[9];
    float* out = (float*)d_out;

    float* h_ptr;
    cudaGetSymbolAddress((void**)&h_ptr, g_h);

    // K1: GroupNorm stats -> per-(b,c) affine
    gn_stats_kernel<<<BATCH * N_GROUPS, 256>>>(x, gn_w, gn_b);
    // K2: FiLM parameters from emb
    emb_gemm_kernel<<<(2 * C_HID) / 8, 256>>>(emb, we, be);
    // K3: out = x + b2
    out_init_kernel<<<(BATCH * C_IN * HW) / (4 * 256), 256>>>(x, b2, out);
    // K4: h_raw = W1 @ GN(x)          (M=1536, N=1024, K=384, per batch)
    gemm_tc_kernel<C_IN, true, false>
        <<<dim3(HW / 128, C_HID / 128, BATCH), 256>>>(w1, x, h_ptr);
    // K5: h = silu(h_raw + b1) * (1+scale) + shift
    mod_silu_kernel<<<(BATCH * C_HID * HW) / (4 * 256), 256>>>(b1);
    // K6: out += W2 @ h               (M=384, N=1024, K=1536, per batch)
    gemm_tc_kernel<C_HID, false, true>
        <<<dim3(HW / 128, C_IN / 128, BATCH), 256>>>(w2, h_ptr, out);
}